// round 16
// baseline (speedup 1.0000x reference)
#include <cuda_runtime.h>
#include <cuda_bf16.h>
#include <cstdint>

// SDPA via mma.sync bf16 hi/lo (3 products ~ fp32 accuracy).
// Prepass converts Q/K/V fp32 -> bf16 hi/lo pitched tile images (ldmatrix-ready)
// in __device__ scratch; main kernel cp.asyncs ready tiles (double-buffered,
// 1 barrier/phase), mask via early direct LDG, GEMM1 -> masked exp -> GEMM2.
// B=32, Q=K=1024, D=64 fp32. out = [context | attn]. mask 4B, nonzero => p=0.
// Main CTA: 32 q rows, 8 warps = (mh 0..1) x (kw 0..3), 16 phases x 64 K-rows.

#define NT 256
#define PITCHB 144               // tile row pitch (bytes)
#define QTILEB (32 * PITCHB)     // 4608
#define KTILEB (64 * PITCHB)     // 9216
#define T4B    (4 * KTILEB)      // 36864: KH,KL,VH,VL per phase

// ---- main-kernel smem ----
#define SM_Q    0                         // QH + QL = 9216
#define SM_T    9216                      // 2 bufs x T4B = 73728
#define SM_Z    (SM_T + 2 * T4B)          // 82944
#define SM_INVZ (SM_Z + 128)
#define SM_CTX  (SM_INVZ + 128)           // 83200, 8192 B
#define SM_TOTAL (SM_CTX + 8192)          // 91392 B (x2 CTAs = 182784)

// ---- device scratch: converted tiles ----
__device__ __align__(16) unsigned char g_kv[32][16][4][KTILEB];
__device__ __align__(16) unsigned char g_q[32][32][2][QTILEB];

__device__ __forceinline__ uint32_t smem_u32(const void* p) {
    uint32_t a;
    asm("{ .reg .u64 t; cvta.to.shared.u64 t, %1; cvt.u32.u64 %0, t; }" : "=r"(a) : "l"(p));
    return a;
}
__device__ __forceinline__ uint32_t b2u(__nv_bfloat162 h) { return *(uint32_t*)&h; }

__device__ __forceinline__ void ldsm_x4(uint32_t a, uint32_t r[4]) {
    asm volatile("ldmatrix.sync.aligned.m8n8.x4.shared.b16 {%0,%1,%2,%3}, [%4];"
                 : "=r"(r[0]), "=r"(r[1]), "=r"(r[2]), "=r"(r[3]) : "r"(a));
}
__device__ __forceinline__ void ldsm_x4t(uint32_t a, uint32_t r[4]) {
    asm volatile("ldmatrix.sync.aligned.m8n8.x4.trans.shared.b16 {%0,%1,%2,%3}, [%4];"
                 : "=r"(r[0]), "=r"(r[1]), "=r"(r[2]), "=r"(r[3]) : "r"(a));
}
__device__ __forceinline__ void mma_bf16(float c[4], const uint32_t a[4], const uint32_t b[2]) {
    asm volatile("mma.sync.aligned.m16n8k16.row.col.f32.bf16.bf16.f32 "
                 "{%0,%1,%2,%3}, {%4,%5,%6,%7}, {%8,%9}, {%0,%1,%2,%3};"
                 : "+f"(c[0]), "+f"(c[1]), "+f"(c[2]), "+f"(c[3])
                 : "r"(a[0]), "r"(a[1]), "r"(a[2]), "r"(a[3]), "r"(b[0]), "r"(b[1]));
}
#define CP16(dst, src) \
    asm volatile("cp.async.cg.shared.global [%0], [%1], 16;" \
                 :: "r"(dst), "l"(__cvta_generic_to_global(src)) : "memory")

__device__ __forceinline__ void split2(float a, float b, uint32_t& h, uint32_t& l) {
    __nv_bfloat162 hh = __floats2bfloat162_rn(a, b);
    __nv_bfloat162 ll = __floats2bfloat162_rn(a - __low2float(hh), b - __high2float(hh));
    h = b2u(hh); l = b2u(ll);
}

// ===================== prepass: fp32 -> bf16 hi/lo tile images =====================
__global__ __launch_bounds__(NT)
void prepass_kernel(const float* __restrict__ Qg, const float* __restrict__ Kg,
                    const float* __restrict__ Vg)
{
    const int bx = blockIdx.x;     // 0..15 KV phase, 16..47 Q tile
    const int b  = blockIdx.y;
    const int tid = threadIdx.x;

    if (bx < 16) {
        const float* Kb = Kg + ((size_t)b * 1024 + bx * 64) * 64;
        const float* Vb = Vg + ((size_t)b * 1024 + bx * 64) * 64;
        unsigned char* kh = g_kv[b][bx][0];
        unsigned char* kl = g_kv[b][bx][1];
        unsigned char* vh = g_kv[b][bx][2];
        unsigned char* vl = g_kv[b][bx][3];
        #pragma unroll
        for (int it = 0; it < 4; it++) {
            int u = tid + it * NT;          // 1024 units
            int row = u >> 4, dg = u & 15;
            int off = row * PITCHB + dg * 8;
            float4 kv = *(const float4*)(Kb + (size_t)row * 64 + dg * 4);
            uint32_t h01, l01, h23, l23;
            split2(kv.x, kv.y, h01, l01);
            split2(kv.z, kv.w, h23, l23);
            *(uint2*)(kh + off) = make_uint2(h01, h23);
            *(uint2*)(kl + off) = make_uint2(l01, l23);
            float4 vv = *(const float4*)(Vb + (size_t)row * 64 + dg * 4);
            split2(vv.x, vv.y, h01, l01);
            split2(vv.z, vv.w, h23, l23);
            *(uint2*)(vh + off) = make_uint2(h01, h23);
            *(uint2*)(vl + off) = make_uint2(l01, l23);
        }
    } else {
        const int qt = bx - 16;
        const float* Qb = Qg + ((size_t)b * 1024 + qt * 32) * 64;
        unsigned char* qh = g_q[b][qt][0];
        unsigned char* ql = g_q[b][qt][1];
        #pragma unroll
        for (int it = 0; it < 2; it++) {
            int u = tid + it * NT;          // 512 units
            int r = u >> 4, dg = u & 15;
            float4 v = *(const float4*)(Qb + (size_t)r * 64 + dg * 4);
            v.x *= 0.125f; v.y *= 0.125f; v.z *= 0.125f; v.w *= 0.125f;
            uint32_t h01, l01, h23, l23;
            split2(v.x, v.y, h01, l01);
            split2(v.z, v.w, h23, l23);
            int off = r * PITCHB + dg * 8;
            *(uint2*)(qh + off) = make_uint2(h01, h23);
            *(uint2*)(ql + off) = make_uint2(l01, l23);
        }
    }
}

// ===================== main kernel =====================
__global__ __launch_bounds__(NT, 2)
void sdpa_mma_kernel(const uint32_t* __restrict__ Mg,
                     float* __restrict__ ctx, float* __restrict__ attn)
{
    extern __shared__ char sm[];
    const uint32_t sb = smem_u32(sm);

    const int tid  = threadIdx.x;
    const int wid  = tid >> 5;
    const int lane = tid & 31;
    const int g    = lane >> 2;
    const int t    = lane & 3;
    const int mh   = wid & 1;
    const int kw   = wid >> 1;

    const int b  = blockIdx.y;
    const int qt = blockIdx.x;
    const int q0 = qt * 32;

    const uint32_t* Mb = Mg + ((size_t)b * 1024 + q0) * 1024;
    float* attnb = attn + ((size_t)b * 1024 + q0) * 1024;
    float* ctxb  = ctx  + ((size_t)b * 1024 + q0) * 64;

    const int r0 = mh * 16 + g;
    const int r1 = r0 + 8;

    if (tid < 32) ((float*)(sm + SM_Z))[tid] = 0.0f;

    // ---- prologue: Q tiles + KV tiles(0) ----
    {
        const unsigned char* gq = g_q[b][qt][0];
        for (int u = tid; u < 576; u += NT)                 // 9216 B
            CP16(sb + SM_Q + u * 16, gq + u * 16);
        const unsigned char* gt = g_kv[b][0][0];
        for (int u = tid; u < 2304; u += NT)                // 36864 B
            CP16(sb + SM_T + u * 16, gt + u * 16);
        asm volatile("cp.async.commit_group;" ::: "memory");
        asm volatile("cp.async.wait_group 0;" ::: "memory");
    }
    __syncthreads();

    // ---- hoist Q fragments ----
    uint32_t QAh[4][4], QAl[4][4];
    #pragma unroll
    for (int kk = 0; kk < 4; kk++) {
        uint32_t arow = (uint32_t)(mh * 16 + (lane & 15)) * PITCHB
                      + (uint32_t)(kk * 16 + 8 * ((lane >> 4) & 1)) * 2;
        ldsm_x4(sb + SM_Q + arow, QAh[kk]);
        ldsm_x4(sb + SM_Q + QTILEB + arow, QAl[kk]);
    }

    float ctxa[8][4];
    #pragma unroll
    for (int j = 0; j < 8; j++)
        #pragma unroll
        for (int i = 0; i < 4; i++) ctxa[j][i] = 0.0f;
    float zr0 = 0.0f, zr1 = 0.0f;

    const uint32_t kfrag_off = (uint32_t)kw * 16 * PITCHB
        + (uint32_t)((lane & 7) + 8 * ((lane >> 4) & 1)) * PITCHB
        + (uint32_t)(8 * ((lane >> 3) & 1)) * 2;
    // x4.trans V base: matrices {0,1} -> n8 tile j2, {2,3} -> tile j2+1
    const uint32_t vfrag_off = 2 * KTILEB
        + (uint32_t)(kw * 16 + (lane & 7) + 8 * ((lane >> 3) & 1)) * PITCHB
        + (uint32_t)((lane >> 4) & 1) * 16;

    for (int ph = 0; ph < 16; ph++) {
        const int buf = ph & 1;

        // issue next-phase tiles into other buffer
        if (ph < 15) {
            const unsigned char* gt = g_kv[b][ph + 1][0];
            uint32_t td = sb + SM_T + (uint32_t)((buf ^ 1) * T4B);
            for (int u = tid; u < 2304; u += NT)
                CP16(td + u * 16, gt + u * 16);
            asm volatile("cp.async.commit_group;" ::: "memory");
        }

        // early mask loads (consumed in epilogue; hidden under GEMM1)
        const int colbase = ph * 64 + kw * 16 + 2 * t;
        uint2 mA0 = __ldg((const uint2*)(Mb + (size_t)r0 * 1024 + colbase));
        uint2 mB0 = __ldg((const uint2*)(Mb + (size_t)r1 * 1024 + colbase));
        uint2 mA1 = __ldg((const uint2*)(Mb + (size_t)r0 * 1024 + colbase + 8));
        uint2 mB1 = __ldg((const uint2*)(Mb + (size_t)r1 * 1024 + colbase + 8));

        const uint32_t tb = sb + SM_T + (uint32_t)(buf * T4B);

        // ---- GEMM1: S(m16 x n16) = Q' @ Kc^T over k=64, 3 products ----
        float S[2][4];
        #pragma unroll
        for (int j = 0; j < 2; j++)
            #pragma unroll
            for (int i = 0; i < 4; i++) S[j][i] = 0.0f;

        #pragma unroll
        for (int kk = 0; kk < 4; kk++) {
            uint32_t ba = tb + kfrag_off + (uint32_t)(kk * 16) * 2;
            uint32_t Bh[4], Bl[4];
            ldsm_x4(ba, Bh);
            ldsm_x4(ba + KTILEB, Bl);
            mma_bf16(S[0], QAh[kk], Bh);
            mma_bf16(S[0], QAh[kk], Bl);
            mma_bf16(S[0], QAl[kk], Bh);
            uint32_t Bh1[2] = { Bh[2], Bh[3] };
            uint32_t Bl1[2] = { Bl[2], Bl[3] };
            mma_bf16(S[1], QAh[kk], Bh1);
            mma_bf16(S[1], QAh[kk], Bl1);
            mma_bf16(S[1], QAl[kk], Bh1);
        }

        // ---- epilogue: mask (regs), exp, unnorm attn, pack P hi/lo ----
        uint32_t Ph0[2], Ph1[2], Pl0[2], Pl1[2];
        {
            #pragma unroll
            for (int j = 0; j < 2; j++) {
                uint2 m0 = j ? mA1 : mA0;
                uint2 m1 = j ? mB1 : mB0;
                int col = colbase + j * 8;
                float p00 = m0.x ? 0.0f : __expf(S[j][0]);
                float p01 = m0.y ? 0.0f : __expf(S[j][1]);
                float p10 = m1.x ? 0.0f : __expf(S[j][2]);
                float p11 = m1.y ? 0.0f : __expf(S[j][3]);
                zr0 += p00 + p01;
                zr1 += p10 + p11;
                *(float2*)(attnb + (size_t)r0 * 1024 + col) = make_float2(p00, p01);
                *(float2*)(attnb + (size_t)r1 * 1024 + col) = make_float2(p10, p11);
                split2(p00, p01, Ph0[j], Pl0[j]);
                split2(p10, p11, Ph1[j], Pl1[j]);
            }
        }

        // ---- GEMM2: ctx += P(m16 x k16) @ Vc(k16 x n64), 3 products ----
        {
            uint32_t Ahf[4] = { Ph0[0], Ph1[0], Ph0[1], Ph1[1] };
            uint32_t Alf[4] = { Pl0[0], Pl1[0], Pl0[1], Pl1[1] };
            #pragma unroll
            for (int s2 = 0; s2 < 4; s2++) {
                uint32_t va = tb + vfrag_off + (uint32_t)(s2 * 32);
                uint32_t Bh[4], Bl[4];
                ldsm_x4t(va, Bh);
                ldsm_x4t(va + KTILEB, Bl);
                uint32_t Bh0[2] = { Bh[0], Bh[1] }, Bh1[2] = { Bh[2], Bh[3] };
                uint32_t Bl0[2] = { Bl[0], Bl[1] }, Bl1[2] = { Bl[2], Bl[3] };
                mma_bf16(ctxa[2 * s2],     Ahf, Bh0);
                mma_bf16(ctxa[2 * s2],     Ahf, Bl0);
                mma_bf16(ctxa[2 * s2],     Alf, Bh0);
                mma_bf16(ctxa[2 * s2 + 1], Ahf, Bh1);
                mma_bf16(ctxa[2 * s2 + 1], Ahf, Bl1);
                mma_bf16(ctxa[2 * s2 + 1], Alf, Bh1);
            }
        }

        if (ph < 15) {
            asm volatile("cp.async.wait_group 0;" ::: "memory");
            __syncthreads();    // next buffer ready; this phase's consumers done
        }
    }

    // ---- Z: quad-reduce then smem atomic ----
    zr0 += __shfl_xor_sync(0xFFFFFFFFu, zr0, 1);
    zr0 += __shfl_xor_sync(0xFFFFFFFFu, zr0, 2);
    zr1 += __shfl_xor_sync(0xFFFFFFFFu, zr1, 1);
    zr1 += __shfl_xor_sync(0xFFFFFFFFu, zr1, 2);
    if (t == 0) {
        atomicAdd((float*)(sm + SM_Z) + r0, zr0);
        atomicAdd((float*)(sm + SM_Z) + r1, zr1);
    }
    __syncthreads();

    if (tid < 32)
        ((float*)(sm + SM_INVZ))[tid] = 1.0f / ((float*)(sm + SM_Z))[tid];
    float* sc = (float*)(sm + SM_CTX);
    #pragma unroll
    for (int it = 0; it < 8; it++) sc[tid + it * NT] = 0.0f;
    __syncthreads();

    // ---- ctx cross-warp reduce (kw quadrants) ----
    #pragma unroll
    for (int j = 0; j < 8; j++) {
        int cb = j * 8 + 2 * t;
        atomicAdd(&sc[r0 * 64 + cb],     ctxa[j][0]);
        atomicAdd(&sc[r0 * 64 + cb + 1], ctxa[j][1]);
        atomicAdd(&sc[r1 * 64 + cb],     ctxa[j][2]);
        atomicAdd(&sc[r1 * 64 + cb + 1], ctxa[j][3]);
    }
    __syncthreads();

    // ---- store ctx (scaled) ----
    const float* inv = (const float*)(sm + SM_INVZ);
    #pragma unroll
    for (int it = 0; it < 8; it++) {
        int u = tid + it * NT;
        int r = u >> 6;
        ctxb[(size_t)r * 64 + (u & 63)] = sc[u] * inv[r];
    }

    // ---- rescale attn tile (L2-hot) ----
    #pragma unroll 4
    for (int it = 0; it < 32; it++) {
        int u = tid + it * NT;
        int r = u >> 8;
        float iz = inv[r];
        float4* p = (float4*)(attnb + (size_t)r * 1024) + (u & 255);
        float4 v = *p;
        v.x *= iz; v.y *= iz; v.z *= iz; v.w *= iz;
        *p = v;
    }
}

extern "C" void kernel_launch(void* const* d_in, const int* in_sizes, int n_in,
                              void* d_out, int out_size) {
    const float* q = (const float*)d_in[0];
    const float* k = (const float*)d_in[1];
    const float* v = (const float*)d_in[2];
    const uint32_t* m = (const uint32_t*)d_in[3];

    float* ctx  = (float*)d_out;
    float* attn = (float*)d_out + 32 * 1024 * 64;

    cudaFuncSetAttribute(sdpa_mma_kernel, cudaFuncAttributeMaxDynamicSharedMemorySize,
                         SM_TOTAL);

    prepass_kernel<<<dim3(48, 32), NT>>>(q, k, v);
    sdpa_mma_kernel<<<dim3(32, 32), NT, SM_TOTAL>>>(m, ctx, attn);
}